// round 7
// baseline (speedup 1.0000x reference)
#include <cuda_runtime.h>
#include <cuda_bf16.h>
#include <cstdint>

// ---------------------------------------------------------------------------
// Problem constants (fixed by setup_inputs)
// ---------------------------------------------------------------------------
#define BB 4
#define DDIM 1024
#define NTOK 2048
static const long DN   = (long)DDIM * NTOK;        // 2,097,152 elems
static const long PER  = (long)BB * DN;            // 8,388,608 elems per tensor
static const long SMAT = (long)NTOK * NTOK;        // 4,194,304 elems per score mat

// ---------------------------------------------------------------------------
// Static device scratch (allocation-rule-safe).
// ---------------------------------------------------------------------------
__device__ __align__(1024) float         g_scores[(size_t)BB * NTOK * NTOK];      // 64MB
__device__ __align__(1024) __nv_bfloat16 g_xT[2][(size_t)BB * NTOK * DDIM];       // x^T hi/lo [b][n][d]
__device__ __align__(1024) __nv_bfloat16 g_W [2][(size_t)3 * DDIM * DDIM];        // Wq|Wk|Wv hi/lo
__device__ __align__(1024) __nv_bfloat16 g_Qt[2][(size_t)BB * NTOK * DDIM];       // Q^T hi/lo
__device__ __align__(1024) __nv_bfloat16 g_Kt[2][(size_t)BB * NTOK * DDIM];       // K^T hi/lo
__device__ __align__(1024) __nv_bfloat16 g_V [2][(size_t)BB * DDIM * NTOK];       // V hi/lo
__device__ __align__(1024) __nv_bfloat16 g_At[2][(size_t)BB * NTOK * NTOK];       // attn^T hi/lo
__device__ __align__(1024) float         g_vsum[(size_t)BB * DDIM];               // rank-1 corr

// ---------------------------------------------------------------------------
// PTX helpers — sm_80-era only (cp.async, ldmatrix, mma.sync). No tcgen05.
// ---------------------------------------------------------------------------
__device__ __forceinline__ uint32_t smem_u32(const void* p) {
    uint32_t a;
    asm("{ .reg .u64 t; cvta.to.shared.u64 t, %1; cvt.u32.u64 %0, t; }" : "=r"(a) : "l"(p));
    return a;
}
__device__ __forceinline__ void cp16(uint32_t dst, const void* src) {
    asm volatile("cp.async.cg.shared.global [%0], [%1], 16;" :: "r"(dst), "l"(src));
}
__device__ __forceinline__ void cp_commit() { asm volatile("cp.async.commit_group;" ::: "memory"); }
__device__ __forceinline__ void cp_wait0()  { asm volatile("cp.async.wait_group 0;" ::: "memory"); }

__device__ __forceinline__ void ldsm4(uint32_t& r0, uint32_t& r1, uint32_t& r2, uint32_t& r3,
                                      uint32_t addr) {
    asm volatile("ldmatrix.sync.aligned.m8n8.x4.shared.b16 {%0,%1,%2,%3}, [%4];"
                 : "=r"(r0), "=r"(r1), "=r"(r2), "=r"(r3) : "r"(addr));
}
__device__ __forceinline__ void mma16816(float* c, const uint32_t* a, uint32_t b0, uint32_t b1) {
    asm volatile(
        "mma.sync.aligned.m16n8k16.row.col.f32.bf16.bf16.f32 "
        "{%0,%1,%2,%3}, {%4,%5,%6,%7}, {%8,%9}, {%0,%1,%2,%3};"
        : "+f"(c[0]), "+f"(c[1]), "+f"(c[2]), "+f"(c[3])
        : "r"(a[0]), "r"(a[1]), "r"(a[2]), "r"(a[3]), "r"(b0), "r"(b1));
}

#define SWZ(o) ((o) ^ (((o) >> 3) & 0x70))

// ---------------------------------------------------------------------------
// bf16-split GEMM via mma.sync.  D[m][n'] = sum_k (Ah+Al)[m][k]*(Bh+Bl)[n'][k]
// (fp32 accum, Al*Bl dropped).  A: [M][K] K-major.  B: [N][K] K-major.
// CTA tile 256x128, 8 warps (4 M x 2 N), warp tile 64x64, K-chunk 64,
// double-buffered cp.async.
//   skip_mf: early-exit tiles fully inside masked quadrant (scores GEMM)
//   kcut_mf: truncate K to mf for B-row tiles >= mf (out GEMM; needs mf%64==0)
//   Ch/Cl:   also emit bf16 hi/lo copies of C (same layout).
// grid = (N/128, M/256, batch), 256 threads.
// ---------------------------------------------------------------------------
#define OFF_AL  32768
#define OFF_BH  65536
#define OFF_BL  81920
#define STAGE   98304           // 96KB per stage
#define GEMM_SMEM (2 * STAGE)   // 192KB

__device__ __forceinline__ void load_chunk(
    uint32_t dstbase,
    const __nv_bfloat16* __restrict__ Ah, const __nv_bfloat16* __restrict__ Al,
    const __nv_bfloat16* __restrict__ Bh, const __nv_bfloat16* __restrict__ Bl,
    int m0, int n0, int k0, int K, int tid)
{
#pragma unroll
    for (int t = 0; t < 24; t++) {
        int s = tid + t * 256;
        const __nv_bfloat16* srcb;
        uint32_t roff;
        int u, rowbase;
        if (t < 8)       { srcb = Ah; roff = 0;      u = s;        rowbase = m0; }
        else if (t < 16) { srcb = Al; roff = OFF_AL; u = s - 2048; rowbase = m0; }
        else if (t < 20) { srcb = Bh; roff = OFF_BH; u = s - 4096; rowbase = n0; }
        else             { srcb = Bl; roff = OFF_BL; u = s - 5120; rowbase = n0; }
        int r = u >> 3, c = u & 7;                 // tile row, 16B chunk within 128B row
        const void* src = srcb + (long)(rowbase + r) * K + k0 + c * 8;
        uint32_t dst = dstbase + roff + SWZ((uint32_t)(r * 128 + c * 16));
        cp16(dst, src);
    }
}

__global__ __launch_bounds__(256, 1)
void gemm_mma(const __nv_bfloat16* __restrict__ Ah, const __nv_bfloat16* __restrict__ Al,
              const __nv_bfloat16* __restrict__ Bh, const __nv_bfloat16* __restrict__ Bl,
              float* __restrict__ C,
              __nv_bfloat16* __restrict__ Ch, __nv_bfloat16* __restrict__ Cl,
              const int* __restrict__ skip_mf, const int* __restrict__ kcut_mf,
              int K, int ldc, long sA, long sB, long sC)
{
    extern __shared__ char smem[];
    const uint32_t sb = smem_u32(smem);
    const int tid = threadIdx.x, wid = tid >> 5, lane = tid & 31;
    const int wm = wid >> 1, wn = wid & 1;         // warp grid 4 (M) x 2 (N)
    const int m0 = blockIdx.y * 256, n0 = blockIdx.x * 128;

    if (skip_mf) {
        int mf = *skip_mf;
        if (m0 >= mf && n0 >= mf) return;          // fully-masked scores tile
    }

    int nk = K >> 6;
    if (kcut_mf) {
        int mf = *kcut_mf;
        if ((mf & 63) == 0 && mf > 0 && mf < K && n0 >= mf)
            nk = mf >> 6;                          // truncated K; rank-1 corr added later
    }

    Ah += (long)blockIdx.z * sA;  Al += (long)blockIdx.z * sA;
    Bh += (long)blockIdx.z * sB;  Bl += (long)blockIdx.z * sB;
    C  += (long)blockIdx.z * sC;
    if (Ch) { Ch += (long)blockIdx.z * sC; Cl += (long)blockIdx.z * sC; }

    float acc[4][8][4];
#pragma unroll
    for (int i = 0; i < 4; i++)
#pragma unroll
        for (int j = 0; j < 8; j++)
#pragma unroll
            for (int q = 0; q < 4; q++) acc[i][j][q] = 0.0f;

    load_chunk(sb, Ah, Al, Bh, Bl, m0, n0, 0, K, tid);
    cp_commit();

    const int a_r = lane & 15;
    const int a_c = lane >> 4;
    const int b_r = ((lane >> 4) << 3) + (lane & 7);
    const int b_c = (lane >> 3) & 1;

    for (int i = 0; i < nk; i++) {
        cp_wait0();
        __syncthreads();
        if (i + 1 < nk) {
            load_chunk(sb + ((i + 1) & 1) * STAGE, Ah, Al, Bh, Bl,
                       m0, n0, (i + 1) << 6, K, tid);
            cp_commit();
        }
        const uint32_t base = sb + (i & 1) * STAGE;

#pragma unroll
        for (int ks = 0; ks < 4; ks++) {
            uint32_t ah[4][4], al[4][4];
#pragma unroll
            for (int mt = 0; mt < 4; mt++) {
                uint32_t o = SWZ((uint32_t)((wm * 64 + mt * 16 + a_r) * 128 + (ks * 2 + a_c) * 16));
                ldsm4(ah[mt][0], ah[mt][1], ah[mt][2], ah[mt][3], base + o);
                ldsm4(al[mt][0], al[mt][1], al[mt][2], al[mt][3], base + OFF_AL + o);
            }
#pragma unroll
            for (int g = 0; g < 4; g++) {          // 4 n16 groups -> warp N=64
                uint32_t bh[4], bl[4];
                uint32_t o = SWZ((uint32_t)((wn * 64 + g * 16 + b_r) * 128 + (ks * 2 + b_c) * 16));
                ldsm4(bh[0], bh[1], bh[2], bh[3], base + OFF_BH + o);
                ldsm4(bl[0], bl[1], bl[2], bl[3], base + OFF_BL + o);
#pragma unroll
                for (int mt = 0; mt < 4; mt++)
#pragma unroll
                    for (int h2 = 0; h2 < 2; h2++) {
                        const int nt = g * 2 + h2;
                        mma16816(acc[mt][nt], ah[mt], bh[h2 * 2], bh[h2 * 2 + 1]);   // Ah*Bh
                        mma16816(acc[mt][nt], ah[mt], bl[h2 * 2], bl[h2 * 2 + 1]);   // Ah*Bl
                        mma16816(acc[mt][nt], al[mt], bh[h2 * 2], bh[h2 * 2 + 1]);   // Al*Bh
                    }
            }
        }
    }

    // Epilogue: fp32 stores (+ optional bf16 hi/lo copies)
    const int erow = lane >> 2;
    const int ecol = (lane & 3) * 2;
#pragma unroll
    for (int mt = 0; mt < 4; mt++) {
#pragma unroll
        for (int nt = 0; nt < 8; nt++) {
            int row = m0 + wm * 64 + mt * 16 + erow;
            int col = n0 + wn * 64 + nt * 8 + ecol;
            long o0 = (long)row * ldc + col;
            long o1 = (long)(row + 8) * ldc + col;
            *(float2*)(C + o0) = make_float2(acc[mt][nt][0], acc[mt][nt][1]);
            *(float2*)(C + o1) = make_float2(acc[mt][nt][2], acc[mt][nt][3]);
            if (Ch) {
                float a0 = acc[mt][nt][0], a1 = acc[mt][nt][1];
                float a2 = acc[mt][nt][2], a3 = acc[mt][nt][3];
                __nv_bfloat16 h0 = __float2bfloat16(a0), h1 = __float2bfloat16(a1);
                __nv_bfloat16 h2 = __float2bfloat16(a2), h3 = __float2bfloat16(a3);
                *(__nv_bfloat162*)(Ch + o0) = __halves2bfloat162(h0, h1);
                *(__nv_bfloat162*)(Ch + o1) = __halves2bfloat162(h2, h3);
                *(__nv_bfloat162*)(Cl + o0) = __halves2bfloat162(
                    __float2bfloat16(a0 - __bfloat162float(h0)),
                    __float2bfloat16(a1 - __bfloat162float(h1)));
                *(__nv_bfloat162*)(Cl + o1) = __halves2bfloat162(
                    __float2bfloat16(a2 - __bfloat162float(h2)),
                    __float2bfloat16(a3 - __bfloat162float(h3)));
            }
        }
    }
}

// ---------------------------------------------------------------------------
// fp32 -> bf16 hi/lo elementwise split
// ---------------------------------------------------------------------------
__global__ void convert_split(const float* __restrict__ in,
                              __nv_bfloat16* __restrict__ oh,
                              __nv_bfloat16* __restrict__ ol, long n)
{
    long i = (long)blockIdx.x * blockDim.x + threadIdx.x;
    if (i >= n) return;
    float f = in[i];
    __nv_bfloat16 h = __float2bfloat16(f);
    __nv_bfloat16 l = __float2bfloat16(f - __bfloat162float(h));
    oh[i] = h;
    ol[i] = l;
}

// ---------------------------------------------------------------------------
// fp32 [R][C] -> bf16 hi/lo transposed [C][R]  (batched over z)
// ---------------------------------------------------------------------------
__global__ __launch_bounds__(256)
void transpose_split(const float* __restrict__ in,
                     __nv_bfloat16* __restrict__ oh, __nv_bfloat16* __restrict__ ol,
                     int R, int C, long si, long so)
{
    __shared__ float t[32][33];
    const float* inb = in + (long)blockIdx.z * si;
    __nv_bfloat16* ohb = oh + (long)blockIdx.z * so;
    __nv_bfloat16* olb = ol + (long)blockIdx.z * so;

    int x = blockIdx.x * 32 + threadIdx.x;
    int y0 = blockIdx.y * 32;
#pragma unroll
    for (int j = threadIdx.y; j < 32; j += 8)
        t[j][threadIdx.x] = inb[(long)(y0 + j) * C + x];
    __syncthreads();
    int ox = blockIdx.y * 32 + threadIdx.x;
    int oy0 = blockIdx.x * 32;
#pragma unroll
    for (int j = threadIdx.y; j < 32; j += 8) {
        float f = t[threadIdx.x][j];
        __nv_bfloat16 h = __float2bfloat16(f);
        __nv_bfloat16 l = __float2bfloat16(f - __bfloat162float(h));
        long o = (long)(oy0 + j) * R + ox;
        ohb[o] = h;
        olb[o] = l;
    }
}

// ---------------------------------------------------------------------------
// Fused: batch-axis softmax (+1/32 scale + hard mask) on fp32 scores,
// then TRANSPOSED bf16 hi/lo write: At[b][m][n] = attn[b][n][m].
// ---------------------------------------------------------------------------
__global__ __launch_bounds__(256)
void softmax_t_kernel(const int* __restrict__ mask_from_p,
                      const float* __restrict__ S,
                      __nv_bfloat16* __restrict__ Ath,
                      __nv_bfloat16* __restrict__ Atl)
{
    __shared__ float a4[BB][32][33];
    const int mf = *mask_from_p;
    const int i0 = blockIdx.y * 32;
    const int j0 = blockIdx.x * 32;
    const int tx = threadIdx.x, ty = threadIdx.y;
    const float scale = 0.03125f;

#pragma unroll
    for (int ii = 0; ii < 4; ii++) {
        int i = i0 + ty + ii * 8;
        int j = j0 + tx;
        long idx = (long)i * NTOK + j;
        float a0, a1, a2, a3;
        if (i >= mf && j >= mf) {
            a0 = a1 = a2 = a3 = 0.25f;
        } else {
            float s0 = S[idx]            * scale;
            float s1 = S[idx + SMAT]     * scale;
            float s2 = S[idx + 2 * SMAT] * scale;
            float s3 = S[idx + 3 * SMAT] * scale;
            float m = fmaxf(fmaxf(s0, s1), fmaxf(s2, s3));
            float e0 = expf(s0 - m), e1 = expf(s1 - m);
            float e2 = expf(s2 - m), e3 = expf(s3 - m);
            float inv = 1.0f / (e0 + e1 + e2 + e3);
            a0 = e0 * inv; a1 = e1 * inv; a2 = e2 * inv; a3 = e3 * inv;
        }
        a4[0][ty + ii * 8][tx] = a0;
        a4[1][ty + ii * 8][tx] = a1;
        a4[2][ty + ii * 8][tx] = a2;
        a4[3][ty + ii * 8][tx] = a3;
    }
    __syncthreads();

#pragma unroll
    for (int jj = 0; jj < 4; jj++) {
        int jm = j0 + ty + jj * 8;
        int in = i0 + tx;
#pragma unroll
        for (int b = 0; b < BB; b++) {
            float v = a4[b][tx][ty + jj * 8];
            __nv_bfloat16 h = __float2bfloat16(v);
            __nv_bfloat16 l = __float2bfloat16(v - __bfloat162float(h));
            long o = (long)b * SMAT + (long)jm * NTOK + in;
            Ath[o] = h;
            Atl[o] = l;
        }
    }
}

// ---------------------------------------------------------------------------
// vsum[b][d] = sum_{n >= mf} V[b][d][n]   (fp32 V from d_out region)
// grid (DDIM, BB), 256 threads
// ---------------------------------------------------------------------------
__global__ __launch_bounds__(256)
void vsum_kernel(const float* __restrict__ V, const int* __restrict__ mfp,
                 float* __restrict__ vs)
{
    __shared__ float red[8];
    const int d = blockIdx.x, b = blockIdx.y;
    int mf = *mfp;
    if (mf < 0) mf = 0;
    float s = 0.0f;
    const float* row = V + (long)b * DN + (long)d * NTOK;
    for (int n = mf + threadIdx.x; n < NTOK; n += 256) s += row[n];
#pragma unroll
    for (int o = 16; o > 0; o >>= 1) s += __shfl_xor_sync(0xFFFFFFFF, s, o);
    if ((threadIdx.x & 31) == 0) red[threadIdx.x >> 5] = s;
    __syncthreads();
    if (threadIdx.x == 0) {
        float t = 0.0f;
#pragma unroll
        for (int w = 0; w < 8; w++) t += red[w];
        vs[(long)b * DDIM + d] = t;
    }
}

// ---------------------------------------------------------------------------
// out[b][d][m] += 0.25 * vsum[b][d]  for tokens m whose 128-tile was truncated
// (predicate matches the GEMM's kcut condition exactly)
// ---------------------------------------------------------------------------
__global__ __launch_bounds__(256)
void addcorr_kernel(float* __restrict__ out, const float* __restrict__ vs,
                    const int* __restrict__ mfp)
{
    const int mf = *mfp;
    if ((mf & 63) != 0 || mf <= 0 || mf >= NTOK) return;   // GEMM didn't truncate
    long i = (long)blockIdx.x * blockDim.x + threadIdx.x;
    if (i >= PER) return;
    int m = (int)(i & (NTOK - 1));
    if ((m & ~127) < mf) return;                           // this tile wasn't truncated
    long bd = i >> 11;                                     // b*DDIM + d
    out[i] += 0.25f * vs[bd];
}

// ---------------------------------------------------------------------------
// kernel_launch
// ---------------------------------------------------------------------------
extern "C" void kernel_launch(void* const* d_in, const int* in_sizes, int n_in,
                              void* d_out, int out_size)
{
    (void)in_sizes; (void)n_in; (void)out_size;
    const float* x   = (const float*)d_in[0];
    const float* W_q = (const float*)d_in[1];
    const float* W_k = (const float*)d_in[2];
    const float* W_v = (const float*)d_in[3];
    const int* mask_from = (const int*)d_in[4];

    float* out = (float*)d_out;
    float* Q   = out + PER;
    float* K   = out + 2 * PER;
    float* V   = out + 3 * PER;

    float* scores;      cudaGetSymbolAddress((void**)&scores, g_scores);
    float* vsum;        cudaGetSymbolAddress((void**)&vsum, g_vsum);
    __nv_bfloat16* xT;  cudaGetSymbolAddress((void**)&xT, g_xT);
    __nv_bfloat16* W;   cudaGetSymbolAddress((void**)&W, g_W);
    __nv_bfloat16* Qt;  cudaGetSymbolAddress((void**)&Qt, g_Qt);
    __nv_bfloat16* Kt;  cudaGetSymbolAddress((void**)&Kt, g_Kt);
    __nv_bfloat16* Vb;  cudaGetSymbolAddress((void**)&Vb, g_V);
    __nv_bfloat16* At;  cudaGetSymbolAddress((void**)&At, g_At);

    const long ndN = (long)BB * NTOK * DDIM;
    const long w1  = (long)DDIM * DDIM;
    const long w3  = 3 * w1;
    const long at1 = (long)BB * NTOK * NTOK;

    __nv_bfloat16 *xTh = xT, *xTl = xT + ndN;
    __nv_bfloat16 *Wh  = W,  *Wl  = W  + w3;
    __nv_bfloat16 *Qth = Qt, *Qtl = Qt + ndN;
    __nv_bfloat16 *Kth = Kt, *Ktl = Kt + ndN;
    __nv_bfloat16 *Vh  = Vb, *Vl  = Vb + ndN;
    __nv_bfloat16 *Ath = At, *Atl = At + at1;

    cudaFuncSetAttribute(gemm_mma, cudaFuncAttributeMaxDynamicSharedMemorySize, GEMM_SMEM);

    // 1) split W's into stacked [3][d][d] bf16 hi/lo
    {
        int th = 256; long n = w1;
        unsigned bl = (unsigned)((n + th - 1) / th);
        convert_split<<<bl, th>>>(W_q, Wh,          Wl,          n);
        convert_split<<<bl, th>>>(W_k, Wh + w1,     Wl + w1,     n);
        convert_split<<<bl, th>>>(W_v, Wh + 2 * w1, Wl + 2 * w1, n);
    }
    // 2) x [b][d][n] -> xT hi/lo [b][n][d]
    {
        dim3 g(NTOK / 32, DDIM / 32, BB);
        transpose_split<<<g, dim3(32, 8)>>>(x, xTh, xTl, DDIM, NTOK, DN, DN);
    }
    // 3) projections (V also emits bf16 hi/lo in epilogue)
    {
        dim3 g(NTOK / 128, DDIM / 256, BB);
        gemm_mma<<<g, 256, GEMM_SMEM>>>(Wh,          Wl,          xTh, xTl, Q,
                                        nullptr, nullptr, nullptr, nullptr, DDIM, NTOK, 0, DN, DN);
        gemm_mma<<<g, 256, GEMM_SMEM>>>(Wh + w1,     Wl + w1,     xTh, xTl, K,
                                        nullptr, nullptr, nullptr, nullptr, DDIM, NTOK, 0, DN, DN);
        gemm_mma<<<g, 256, GEMM_SMEM>>>(Wh + 2 * w1, Wl + 2 * w1, xTh, xTl, V,
                                        Vh, Vl, nullptr, nullptr, DDIM, NTOK, 0, DN, DN);
    }
    // 4) Q,K -> transposed hi/lo
    {
        dim3 g(NTOK / 32, DDIM / 32, BB);
        transpose_split<<<g, dim3(32, 8)>>>(Q, Qth, Qtl, DDIM, NTOK, DN, DN);
        transpose_split<<<g, dim3(32, 8)>>>(K, Kth, Ktl, DDIM, NTOK, DN, DN);
    }
    // 5) scores = Qt * Kt^T (skip fully-masked tiles)
    {
        dim3 g(NTOK / 128, NTOK / 256, BB);
        gemm_mma<<<g, 256, GEMM_SMEM>>>(Qth, Qtl, Kth, Ktl, scores,
                                        nullptr, nullptr, mask_from, nullptr, DDIM, NTOK, DN, DN, SMAT);
    }
    // 6) fused batch softmax + transpose + bf16 split -> At hi/lo
    {
        dim3 g(NTOK / 32, NTOK / 32);
        softmax_t_kernel<<<g, dim3(32, 8)>>>(mask_from, scores, Ath, Atl);
    }
    // 7) rank-1 correction inputs: vsum[b][d] = sum_{n>=mf} V
    {
        dim3 g(DDIM, BB);
        vsum_kernel<<<g, 256>>>(V, mask_from, vsum);
    }
    // 8) out = V * attn  (K truncated to mf for token-tiles >= mf)
    {
        dim3 g(NTOK / 128, DDIM / 256, BB);
        gemm_mma<<<g, 256, GEMM_SMEM>>>(Vh, Vl, Ath, Atl, out,
                                        nullptr, nullptr, nullptr, mask_from, NTOK, NTOK, DN, SMAT, DN);
    }
    // 9) add 0.25 * vsum to truncated token columns
    {
        long total = PER;
        addcorr_kernel<<<(unsigned)((total + 255) / 256), 256>>>(out, vsum, mask_from);
    }
}